// round 6
// baseline (speedup 1.0000x reference)
#include <cuda_runtime.h>

// PositionalEncodingLayer: out[b,t,d] = X[b,t,d] + pe[t,d]
//   pe[t, 2i]   = sin(t / 10000^(2i/d))
//   pe[t, 2i+1] = cos(t / 10000^(2i/d))
// B=8, T=4096, D=1024, fp32.
//
// Round 6 = Round 5 resubmitted (R5 bench was an infra failure: container
// died twice, kernel never ran — same flake signature as R3, whose
// resubmission then ran fine).
//
// Persistent grid-stride: R4 falsified the occupancy theory (occ 41->62%,
// DRAM only 68->70%): we're near the mixed read+write HBM ceiling. Remaining
// lever = wave structure: grid=4096 at 6 blocks/SM was 4.6 waves with
// cold-start latency bubbles at each transition. Launch exactly one resident
// wave (grid = 148 SMs * 6 = 888) and grid-stride over rows, so every CTA
// slot streams continuously and iteration t+1's loads overlap iteration t's
// stores.

constexpr int Bn  = 8;
constexpr int Tn  = 4096;
constexpr int Dn  = 1024;
constexpr int C4  = Dn / 4;            // 256 float4 chunks per row
constexpr int PLANE4 = Tn * C4;        // float4 per batch plane (1,048,576)
constexpr int GRID = 148 * 6;          // one full resident wave (B200: 148 SMs)

__global__ __launch_bounds__(C4, 6)
void pe_add_kernel(const float4* __restrict__ X, float4* __restrict__ O)
{
    const int j = threadIdx.x;             // column chunk: cols 4j..4j+3

    // Thread-invariant frequency setup (hoisted out of the row loop).
    // inv_freq_i = 10000^(-2i/D) = exp2(-i * 2*log2(10000)/D)
    const float k  = 0.02595256306250292f; // 2*log2(10000)/1024
    const float i0 = (float)(2 * j);
    const float f0 = exp2f(-i0 * k);
    const float f1 = exp2f(-(i0 + 1.0f) * k);

    for (int t = blockIdx.x; t < Tn; t += GRID) {
        const int idx = t * C4 + j;        // fits in int32 (max 8M)
        const float4* xin = X + idx;
        float4*       out = O + idx;

        // Stage 1: first 4 batch planes in flight while trig computes.
        float4 v0 = __ldcs(xin + 0 * PLANE4);
        float4 v1 = __ldcs(xin + 1 * PLANE4);
        float4 v2 = __ldcs(xin + 2 * PLANE4);
        float4 v3 = __ldcs(xin + 3 * PLANE4);

        float s0, c0, s1, c1;
        sincosf((float)t * f0, &s0, &c0);
        sincosf((float)t * f1, &s1, &c1);

        // Stage 2 loads interleaved with stage-1 stores; 4 live float4 max.
        v0.x += s0; v0.y += c0; v0.z += s1; v0.w += c1;
        __stcs(out + 0 * PLANE4, v0);
        float4 v4 = __ldcs(xin + 4 * PLANE4);

        v1.x += s0; v1.y += c0; v1.z += s1; v1.w += c1;
        __stcs(out + 1 * PLANE4, v1);
        float4 v5 = __ldcs(xin + 5 * PLANE4);

        v2.x += s0; v2.y += c0; v2.z += s1; v2.w += c1;
        __stcs(out + 2 * PLANE4, v2);
        float4 v6 = __ldcs(xin + 6 * PLANE4);

        v3.x += s0; v3.y += c0; v3.z += s1; v3.w += c1;
        __stcs(out + 3 * PLANE4, v3);
        float4 v7 = __ldcs(xin + 7 * PLANE4);

        v4.x += s0; v4.y += c0; v4.z += s1; v4.w += c1;
        __stcs(out + 4 * PLANE4, v4);
        v5.x += s0; v5.y += c0; v5.z += s1; v5.w += c1;
        __stcs(out + 5 * PLANE4, v5);
        v6.x += s0; v6.y += c0; v6.z += s1; v6.w += c1;
        __stcs(out + 6 * PLANE4, v6);
        v7.x += s0; v7.y += c0; v7.z += s1; v7.w += c1;
        __stcs(out + 7 * PLANE4, v7);
    }
}

extern "C" void kernel_launch(void* const* d_in, const int* in_sizes, int n_in,
                              void* d_out, int out_size)
{
    (void)in_sizes; (void)n_in; (void)out_size;
    const float4* X = (const float4*)d_in[0];
    float4*       O = (float4*)d_out;
    pe_add_kernel<<<GRID, C4>>>(X, O);
}

// round 9
// speedup vs baseline: 1.1486x; 1.1486x over previous
#include <cuda_runtime.h>

// PositionalEncodingLayer: out[b,t,d] = X[b,t,d] + pe[t,d]
//   pe[t, 2i]   = sin(t / 10000^(2i/d))
//   pe[t, 2i+1] = cos(t / 10000^(2i/d))
// B=8, T=4096, D=1024, fp32.
//
// Round 9: hybrid of the two best measured forms (R2: 45.3us, MLP_p1=8,
// occ 41%; R4: 45.5us, MLP_p1=4, occ 62%). Take R2's all-loads-first
// structure (maximal front-batched memory parallelism, loads independent of
// trig) and add R4's occupancy via __launch_bounds__(256, 5) -> 48-reg cap
// -> 5 blocks/SM (~62% theoretical occ). 8 live float4 = 32 regs + ~14
// trig/addressing fits in 48 without spills.
//
// Evidence so far: occupancy alone falsified (R4), persistence falsified
// (R6, regressed); effective BW ~7.0 TB/s = ~87% of spec, near the mixed
// read+write HBM3e ceiling. This round tests the joint MLP x occupancy
// lever and doubles as the plateau lock-in run.

constexpr int Bn  = 8;
constexpr int Tn  = 4096;
constexpr int Dn  = 1024;
constexpr int C4  = Dn / 4;            // 256 float4 chunks per row
constexpr int PLANE4 = Tn * C4;        // float4 per batch plane (1,048,576)

__global__ __launch_bounds__(C4, 5)
void pe_add_kernel(const float4* __restrict__ X, float4* __restrict__ O)
{
    const int j = threadIdx.x;             // column chunk: cols 4j..4j+3
    const int t = blockIdx.x;              // row
    const int idx = t * C4 + j;            // fits in int32 (max 8M)

    // Issue all 8 loads up front — independent, front-batched MLP=8.
    float4 x[Bn];
    #pragma unroll
    for (int b = 0; b < Bn; ++b)
        x[b] = __ldcs(&X[idx + b * PLANE4]);

    // pe for this thread's 4 columns, computed under the load latency.
    // inv_freq_i = 10000^(-2i/D) = exp2(-i * 2*log2(10000)/D)
    const float k  = 0.02595256306250292f; // 2*log2(10000)/1024
    const float i0 = (float)(2 * j);
    const float f0 = exp2f(-i0 * k);
    const float f1 = exp2f(-(i0 + 1.0f) * k);
    float s0, c0, s1, c1;
    sincosf((float)t * f0, &s0, &c0);
    sincosf((float)t * f1, &s1, &c1);

    #pragma unroll
    for (int b = 0; b < Bn; ++b) {
        float4 v = x[b];
        v.x += s0; v.y += c0; v.z += s1; v.w += c1;
        __stcs(&O[idx + b * PLANE4], v);
    }
}

extern "C" void kernel_launch(void* const* d_in, const int* in_sizes, int n_in,
                              void* d_out, int out_size)
{
    (void)in_sizes; (void)n_in; (void)out_size;
    const float4* X = (const float4*)d_in[0];
    float4*       O = (float4*)d_out;
    pe_add_kernel<<<Tn, C4>>>(X, O);
}

// round 12
// speedup vs baseline: 1.1695x; 1.0182x over previous
#include <cuda_runtime.h>

// PositionalEncodingLayer: out[b,t,d] = X[b,t,d] + pe[t,d]
//   pe[t, 2i]   = sin(t / 10000^(2i/d))
//   pe[t, 2i+1] = cos(t / 10000^(2i/d))
// B=8, T=4096, D=1024, fp32.
//
// FINAL FORM = R2 configuration (best measured bench: 45.34us; kernel
// 38.8us, regs 52, occ 41%, DRAM 68%). Statistically tied with the R4
// 2-stage pipeline (bench 45.50us, kernel 38.3us); R2 holds the best
// bench-metric number.
//
// Session evidence — every structural lever tested and exhausted:
//  - R4: occupancy falsified (occ 41->62% moved DRAM only 68->70%)
//  - R6: persistence falsified (one-wave grid-stride regressed to 46.6us;
//        per-SM CTA injection with front-batched loads IS the latency hiding)
//  - R9: joint MLP8 x occupancy-cap falsified (regressed to 39.8us)
// Wall-clock effective BW = 268MB / ~38.5us = ~7.0 TB/s = ~87% of spec:
// pinned at the mixed read+write HBM3e turnaround ceiling. Traffic is
// irreducible (pure broadcast add: 128MB in + 128MB out, pe computed
// in-register).
//
// Structure: grid=4096 (one row per CTA), 256 threads (one float4 chunk
// per thread). All 8 batch-plane loads front-batched (MLP=8) so the ~600cy
// DRAM latency overlaps the two sincosf; add + streaming stores follow.
//
// (Rounds 3/5/7/8/10/11 were broker-side container flakes — including R11
// on these exact bytes, which ran cleanly in R2: failures are
// content-independent.)

constexpr int Bn  = 8;
constexpr int Tn  = 4096;
constexpr int Dn  = 1024;
constexpr int C4  = Dn / 4;            // 256 float4 chunks per row
constexpr int PLANE4 = Tn * C4;        // float4 per batch plane (1,048,576)

__global__ __launch_bounds__(C4)
void pe_add_kernel(const float4* __restrict__ X, float4* __restrict__ O)
{
    const int j = threadIdx.x;             // column chunk: cols 4j..4j+3
    const int t = blockIdx.x;              // row
    const int idx = t * C4 + j;            // fits in int32 (max 8M)

    // Issue all 8 loads up front — independent, front-batched MLP.
    float4 x[Bn];
    #pragma unroll
    for (int b = 0; b < Bn; ++b)
        x[b] = __ldcs(&X[idx + b * PLANE4]);

    // pe for this thread's 4 columns (pair 2j -> sin/cos, pair 2j+1 -> sin/cos)
    // inv_freq_i = 10000^(-2i/D) = exp2(-i * 2*log2(10000)/D)
    const float k  = 0.02595256306250292f; // 2*log2(10000)/1024
    const float i0 = (float)(2 * j);
    const float f0 = exp2f(-i0 * k);
    const float f1 = exp2f(-(i0 + 1.0f) * k);
    float s0, c0, s1, c1;
    sincosf((float)t * f0, &s0, &c0);
    sincosf((float)t * f1, &s1, &c1);

    #pragma unroll
    for (int b = 0; b < Bn; ++b) {
        float4 v = x[b];
        v.x += s0; v.y += c0; v.z += s1; v.w += c1;
        __stcs(&O[idx + b * PLANE4], v);
    }
}

extern "C" void kernel_launch(void* const* d_in, const int* in_sizes, int n_in,
                              void* d_out, int out_size)
{
    (void)in_sizes; (void)n_in; (void)out_size;
    const float4* X = (const float4*)d_in[0];
    float4*       O = (float4*)d_out;
    pe_add_kernel<<<Tn, C4>>>(X, O);
}

// round 13
// speedup vs baseline: 1.1819x; 1.0106x over previous
#include <cuda_runtime.h>

// PositionalEncodingLayer: out[b,t,d] = X[b,t,d] + pe[t,d]
//   pe[t, 2i]   = sin(t / 10000^(2i/d))
//   pe[t, 2i+1] = cos(t / 10000^(2i/d))
// B=8, T=4096, D=1024, fp32.
//
// CONVERGED FINAL FORM (R2 = R12 bytes). Measured twice:
//   R2:  bench 45.34us, kernel 38.75us
//   R12: bench 45.70us, kernel 37.86us  (best kernel time of session)
// Run-to-run bench noise ~±0.4us exceeds all inter-form differences.
// Wall-clock effective BW = 268MB / 37.9us = 7.08 TB/s = 88.5% of spec:
// pinned at the mixed read+write HBM3e turnaround ceiling.
//
// Session evidence — every structural lever tested and falsified:
//  - R4: occupancy (occ 41->62% moved DRAM only 68->70%, bench flat)
//  - R6: persistence (one-wave grid-stride regressed to 53.4us; per-SM CTA
//        injection with front-batched loads IS the latency-hiding mechanism)
//  - R9: joint MLP8 x occupancy-cap (regressed to 46.5us; reg-cap squeeze)
// Traffic is irreducible: 128MB in + 128MB out, pe computed in-register
// (fma pipe 6% busy), and the LTS/DRAM path is access-mechanism-independent
// so hint/TMA variants cannot move the ceiling.
//
// Structure: grid=4096 (one row per CTA), 256 threads (one float4 chunk per
// thread). All 8 batch-plane loads front-batched (MLP=8) so the ~600cy DRAM
// latency overlaps the two sincosf; add + streaming stores follow.

constexpr int Bn  = 8;
constexpr int Tn  = 4096;
constexpr int Dn  = 1024;
constexpr int C4  = Dn / 4;            // 256 float4 chunks per row
constexpr int PLANE4 = Tn * C4;        // float4 per batch plane (1,048,576)

__global__ __launch_bounds__(C4)
void pe_add_kernel(const float4* __restrict__ X, float4* __restrict__ O)
{
    const int j = threadIdx.x;             // column chunk: cols 4j..4j+3
    const int t = blockIdx.x;              // row
    const int idx = t * C4 + j;            // fits in int32 (max 8M)

    // Issue all 8 loads up front — independent, front-batched MLP.
    float4 x[Bn];
    #pragma unroll
    for (int b = 0; b < Bn; ++b)
        x[b] = __ldcs(&X[idx + b * PLANE4]);

    // pe for this thread's 4 columns (pair 2j -> sin/cos, pair 2j+1 -> sin/cos)
    // inv_freq_i = 10000^(-2i/D) = exp2(-i * 2*log2(10000)/D)
    const float k  = 0.02595256306250292f; // 2*log2(10000)/1024
    const float i0 = (float)(2 * j);
    const float f0 = exp2f(-i0 * k);
    const float f1 = exp2f(-(i0 + 1.0f) * k);
    float s0, c0, s1, c1;
    sincosf((float)t * f0, &s0, &c0);
    sincosf((float)t * f1, &s1, &c1);

    #pragma unroll
    for (int b = 0; b < Bn; ++b) {
        float4 v = x[b];
        v.x += s0; v.y += c0; v.z += s1; v.w += c1;
        __stcs(&O[idx + b * PLANE4], v);
    }
}

extern "C" void kernel_launch(void* const* d_in, const int* in_sizes, int n_in,
                              void* d_out, int out_size)
{
    (void)in_sizes; (void)n_in; (void)out_size;
    const float4* X = (const float4*)d_in[0];
    float4*       O = (float4*)d_out;
    pe_add_kernel<<<Tn, C4>>>(X, O);
}